// round 8
// baseline (speedup 1.0000x reference)
#include <cuda_runtime.h>
#include <cuda_fp16.h>
#include <cstdint>

// ---------------------------------------------------------------------------
// Fixed problem dims
// ---------------------------------------------------------------------------
static constexpr int M = 8192;
static constexpr int K = 4096;
static constexpr int N = 11008;

// Scratch: xh = fp16(x); wh = fp16(W + 2*B@A)
__device__ __half g_Xh[(size_t)M * K];
__device__ __half g_Wh[(size_t)N * K];

// ---------------------------------------------------------------------------
// Prologue 1: convert X to fp16
// ---------------------------------------------------------------------------
__global__ void conv_x_kernel(const float4* __restrict__ X, size_t n4) {
    size_t i = (size_t)blockIdx.x * blockDim.x + threadIdx.x;
    if (i >= n4) return;
    float4 v = X[i];
    __half2* Xh2 = reinterpret_cast<__half2*>(g_Xh);
    Xh2[2 * i]     = __floats2half2_rn(v.x, v.y);
    Xh2[2 * i + 1] = __floats2half2_rn(v.z, v.w);
}

// ---------------------------------------------------------------------------
// Prologue 2: Weff = W + 2.0*(B@A) -> fp16
// ---------------------------------------------------------------------------
static constexpr int FO = 32;
static constexpr int FI = 512;

__global__ void fold_w_kernel(const float* __restrict__ W,
                              const float* __restrict__ Bm,
                              const float* __restrict__ Am) {
    __shared__ float sA[16][FI];
    __shared__ float sB[FO][16];
    const int iBase = blockIdx.x * FI;
    const int oBase = blockIdx.y * FO;
    const int tid = threadIdx.x;

    for (int j = tid; j < 16 * FI; j += 256) {
        int r = j / FI, i = j % FI;
        sA[r][i] = Am[(size_t)r * K + iBase + i];
    }
    for (int j = tid; j < FO * 16; j += 256) {
        int o = j / 16, r = j % 16;
        sB[o][r] = Bm[(size_t)(oBase + o) * 16 + r];
    }
    __syncthreads();

    #pragma unroll 4
    for (int e = 0; e < (FO * FI) / 256; e++) {
        int idx = tid + 256 * e;
        int oo = idx / FI, ii = idx % FI;
        size_t g = (size_t)(oBase + oo) * K + iBase + ii;
        float acc = W[g];
        #pragma unroll
        for (int r = 0; r < 16; r++) acc += 2.0f * sB[oo][r] * sA[r][ii];
        g_Wh[g] = __float2half_rn(acc);
    }
}

// ---------------------------------------------------------------------------
// Main GEMM: C = Xh@Wh^T + bias  (single-pass fp16, fp32 accumulate)
// CTA 256x128, warp 64x64 (8 warps 4x2), BK=64, ldmatrix.x4, 3-stage cp.async,
// ONE __syncthreads per stage. SMEM rows: 64 halves = 128B data + 16B pad =
// 144B stride; 144*i mod 128 covers all 8 16B-phases -> conflict-free LDSM.
// ---------------------------------------------------------------------------
static constexpr int BM = 256, BN = 128, BK = 64;
static constexpr int TM_TILES = M / BM;   // 32
static constexpr int TN_TILES = N / BN;   // 86
static constexpr int NSTAGES_K = K / BK;  // 64

static constexpr int ROWB = 144;
static constexpr int TILE_X = BM * ROWB;              // 36864
static constexpr int TILE_W = BN * ROWB;              // 18432
static constexpr int OFF_X = 0;
static constexpr int OFF_W = TILE_X;
static constexpr int STAGE_BYTES = TILE_X + TILE_W;   // 55296
static constexpr int NSLOTS = 3;
static constexpr int SMEM_TOTAL = NSLOTS * STAGE_BYTES;  // 165888

#define MMA_FP16(d, a, b)                                                      \
    asm volatile(                                                              \
        "mma.sync.aligned.m16n8k16.row.col.f32.f16.f16.f32 "                   \
        "{%0,%1,%2,%3}, {%4,%5,%6,%7}, {%8,%9}, {%0,%1,%2,%3};"                \
        : "+f"((d)[0]), "+f"((d)[1]), "+f"((d)[2]), "+f"((d)[3])               \
        : "r"((a)[0]), "r"((a)[1]), "r"((a)[2]), "r"((a)[3]),                  \
          "r"((b)[0]), "r"((b)[1]))

#define LDSM_X4(r0, r1, r2, r3, addr)                                          \
    asm volatile("ldmatrix.sync.aligned.m8n8.x4.shared.b16 {%0,%1,%2,%3}, [%4];" \
                 : "=r"(r0), "=r"(r1), "=r"(r2), "=r"(r3) : "r"(addr))

__device__ __forceinline__ void cp16(uint32_t sdst, const void* g) {
    asm volatile("cp.async.cg.shared.global [%0], [%1], 16;" :: "r"(sdst), "l"(g));
}
#define CP_COMMIT() asm volatile("cp.async.commit_group;" ::: "memory")
#define CP_WAIT(n) asm volatile("cp.async.wait_group %0;" :: "n"(n) : "memory")

__device__ __forceinline__ void issue_stage(uint32_t tb, int k0,
                                            const __half* gX, const __half* gW,
                                            int tid) {
    // X: 256 rows x 8 chunks = 2048; W: 128 rows x 8 = 1024
    #pragma unroll
    for (int j = 0; j < 8; j++) {
        int q = tid + 256 * j;
        int r = q >> 3, c = q & 7;
        cp16(tb + OFF_X + r * ROWB + c * 16, gX + (size_t)r * K + k0 + c * 8);
    }
    #pragma unroll
    for (int j = 0; j < 4; j++) {
        int q = tid + 256 * j;
        int r = q >> 3, c = q & 7;
        cp16(tb + OFF_W + r * ROWB + c * 16, gW + (size_t)r * K + k0 + c * 8);
    }
    CP_COMMIT();
}

__device__ __forceinline__ void compute_stage(uint32_t tb, int wm, int wn, int lane,
                                              float acc[4][8][4]) {
    const int lrow = lane & 15;
    const int lcol = lane >> 4;  // which 8-elem k-half within k16 fragment
    #pragma unroll
    for (int kk = 0; kk < 4; kk++) {
        const uint32_t kbyte = kk * 32 + lcol * 16;

        // B fragments: warp covers 64 N-rows = 4 LDSM.x4 groups of 16
        uint32_t bh[8][2];
        #pragma unroll
        for (int np = 0; np < 4; np++) {
            uint32_t base = tb + OFF_W + (wn * 64 + np * 16 + lrow) * ROWB + kbyte;
            uint32_t t0, t1, t2, t3;
            LDSM_X4(t0, t1, t2, t3, base);
            bh[2 * np][0] = t0; bh[2 * np + 1][0] = t1;
            bh[2 * np][1] = t2; bh[2 * np + 1][1] = t3;
        }

        // A fragments + MMAs: 4 m-tiles of 16 rows
        #pragma unroll
        for (int mt = 0; mt < 4; mt++) {
            uint32_t base = tb + OFF_X + (wm * 64 + mt * 16 + lrow) * ROWB + kbyte;
            uint32_t ah[4];
            LDSM_X4(ah[0], ah[1], ah[2], ah[3], base);
            #pragma unroll
            for (int nt = 0; nt < 8; nt++) {
                MMA_FP16(acc[mt][nt], ah, bh[nt]);
            }
        }
    }
}

__global__ __launch_bounds__(256, 1)
void gemm_fp16_kernel(const float* __restrict__ bias, float* __restrict__ C) {
    extern __shared__ __align__(1024) char smem[];
    uint32_t sb;
    asm("{ .reg .u64 t; cvta.to.shared.u64 t, %1; cvt.u32.u64 %0, t; }"
        : "=r"(sb) : "l"(smem));

    const int tid = threadIdx.x;
    const int warp = tid >> 5;
    const int lane = tid & 31;
    const int wm = warp >> 1;  // 0..3 (64 rows each)
    const int wn = warp & 1;   // 0..1 (64 cols each)

    // Supertile raster: groups of 8 N-tiles, M-major (32 m-tiles) within group
    int lin = blockIdx.x;
    int gid = lin >> 8;             // / (8*32)
    int rem = lin & 255;
    int n0 = gid * 8;
    int width = min(8, TN_TILES - n0);
    int mT = rem / width;
    int nT = n0 + rem % width;
    const int mBase = mT * BM;
    const int nBase = nT * BN;

    const __half* gX = g_Xh + (size_t)mBase * K;
    const __half* gW = g_Wh + (size_t)nBase * K;

    float acc[4][8][4];
    #pragma unroll
    for (int a = 0; a < 4; a++)
        #pragma unroll
        for (int b = 0; b < 8; b++)
            #pragma unroll
            for (int c = 0; c < 4; c++) acc[a][b][c] = 0.0f;

    issue_stage(sb + 0 * STAGE_BYTES, 0 * BK, gX, gW, tid);
    issue_stage(sb + 1 * STAGE_BYTES, 1 * BK, gX, gW, tid);

    int slot = 0;
    for (int s = 0; s < NSTAGES_K; s++) {
        if (s + 1 < NSTAGES_K) { CP_WAIT(1); } else { CP_WAIT(0); }
        __syncthreads();   // single barrier: also guards reuse of slot (s+2)%3,
                           // which was last read by compute at iteration s-1
        if (s + 2 < NSTAGES_K) {
            int wslot = slot + 2; if (wslot >= NSLOTS) wslot -= NSLOTS;
            issue_stage(sb + wslot * STAGE_BYTES, (s + 2) * BK, gX, gW, tid);
        }
        compute_stage(sb + slot * STAGE_BYTES, wm, wn, lane, acc);
        slot++;
        if (slot == NSLOTS) slot = 0;
    }

    // Epilogue: add bias, write fp32
    const int qrow = lane >> 2;
    const int qc = (lane & 3) * 2;
    #pragma unroll
    for (int nt = 0; nt < 8; nt++) {
        int col = nBase + wn * 64 + nt * 8 + qc;
        float2 bs = *(const float2*)(bias + col);
        #pragma unroll
        for (int mt = 0; mt < 4; mt++) {
            int row = mBase + wm * 64 + mt * 16 + qrow;
            float2 v0 = make_float2(acc[mt][nt][0] + bs.x, acc[mt][nt][1] + bs.y);
            float2 v1 = make_float2(acc[mt][nt][2] + bs.x, acc[mt][nt][3] + bs.y);
            *(float2*)(C + (size_t)row * N + col) = v0;
            *(float2*)(C + (size_t)(row + 8) * N + col) = v1;
        }
    }
}

// ---------------------------------------------------------------------------
// Launch
// ---------------------------------------------------------------------------
extern "C" void kernel_launch(void* const* d_in, const int* in_sizes, int n_in,
                              void* d_out, int out_size) {
    const float* x    = (const float*)d_in[0];
    const float* W    = (const float*)d_in[1];
    const float* bias = (const float*)d_in[2];
    const float* B    = (const float*)d_in[3];
    const float* A    = (const float*)d_in[4];
    float* out = (float*)d_out;

    size_t n4 = (size_t)M * K / 4;
    conv_x_kernel<<<(unsigned)((n4 + 255) / 256), 256>>>((const float4*)x, n4);
    fold_w_kernel<<<dim3(K / FI, N / FO), 256>>>(W, B, A);

    cudaFuncSetAttribute(gemm_fp16_kernel,
                         cudaFuncAttributeMaxDynamicSharedMemorySize, SMEM_TOTAL);
    gemm_fp16_kernel<<<TM_TILES * TN_TILES, 256, SMEM_TOTAL>>>(bias, out);
}

// round 9
// speedup vs baseline: 1.0309x; 1.0309x over previous
#include <cuda_runtime.h>
#include <cuda_fp16.h>
#include <cstdint>

// ---------------------------------------------------------------------------
// Fixed problem dims
// ---------------------------------------------------------------------------
static constexpr int M = 8192;
static constexpr int K = 4096;
static constexpr int N = 11008;

// Scratch: xh = fp16(x); wh = fp16(W + 2*B@A)
__device__ __half g_Xh[(size_t)M * K];
__device__ __half g_Wh[(size_t)N * K];

// ---------------------------------------------------------------------------
// Prologue 1: convert X to fp16
// ---------------------------------------------------------------------------
__global__ void conv_x_kernel(const float4* __restrict__ X, size_t n4) {
    size_t i = (size_t)blockIdx.x * blockDim.x + threadIdx.x;
    if (i >= n4) return;
    float4 v = X[i];
    __half2* Xh2 = reinterpret_cast<__half2*>(g_Xh);
    Xh2[2 * i]     = __floats2half2_rn(v.x, v.y);
    Xh2[2 * i + 1] = __floats2half2_rn(v.z, v.w);
}

// ---------------------------------------------------------------------------
// Prologue 2: Weff = W + 2.0*(B@A) -> fp16
// ---------------------------------------------------------------------------
static constexpr int FO = 32;
static constexpr int FI = 512;

__global__ void fold_w_kernel(const float* __restrict__ W,
                              const float* __restrict__ Bm,
                              const float* __restrict__ Am) {
    __shared__ float sA[16][FI];
    __shared__ float sB[FO][16];
    const int iBase = blockIdx.x * FI;
    const int oBase = blockIdx.y * FO;
    const int tid = threadIdx.x;

    for (int j = tid; j < 16 * FI; j += 256) {
        int r = j / FI, i = j % FI;
        sA[r][i] = Am[(size_t)r * K + iBase + i];
    }
    for (int j = tid; j < FO * 16; j += 256) {
        int o = j / 16, r = j % 16;
        sB[o][r] = Bm[(size_t)(oBase + o) * 16 + r];
    }
    __syncthreads();

    #pragma unroll 4
    for (int e = 0; e < (FO * FI) / 256; e++) {
        int idx = tid + 256 * e;
        int oo = idx / FI, ii = idx % FI;
        size_t g = (size_t)(oBase + oo) * K + iBase + ii;
        float acc = W[g];
        #pragma unroll
        for (int r = 0; r < 16; r++) acc += 2.0f * sB[oo][r] * sA[r][ii];
        g_Wh[g] = __float2half_rn(acc);
    }
}

// ---------------------------------------------------------------------------
// Main GEMM: C = Xh@Wh^T + bias  (single-pass fp16, fp32 accumulate)
// CTA 128x128, 4 warps of 64x64 (2x2), 128 threads, BK=64, 3-stage cp.async,
// register double-buffered fragments, 2 CTAs/SM.
// SMEM rows: 64 halves = 128B data + 16B pad = 144B stride; conflict-free LDSM.
// ---------------------------------------------------------------------------
static constexpr int BM = 128, BN = 128, BK = 64;
static constexpr int TM_TILES = M / BM;   // 64
static constexpr int TN_TILES = N / BN;   // 86
static constexpr int NSTAGES_K = K / BK;  // 64

static constexpr int ROWB = 144;
static constexpr int TILE_X = BM * ROWB;              // 18432
static constexpr int TILE_W = BN * ROWB;              // 18432
static constexpr int OFF_X = 0;
static constexpr int OFF_W = TILE_X;
static constexpr int STAGE_BYTES = TILE_X + TILE_W;   // 36864
static constexpr int NSLOTS = 3;
static constexpr int SMEM_TOTAL = NSLOTS * STAGE_BYTES;  // 110592 -> 2 CTAs/SM

#define MMA_FP16(d, a, b)                                                      \
    asm volatile(                                                              \
        "mma.sync.aligned.m16n8k16.row.col.f32.f16.f16.f32 "                   \
        "{%0,%1,%2,%3}, {%4,%5,%6,%7}, {%8,%9}, {%0,%1,%2,%3};"                \
        : "+f"((d)[0]), "+f"((d)[1]), "+f"((d)[2]), "+f"((d)[3])               \
        : "r"((a)[0]), "r"((a)[1]), "r"((a)[2]), "r"((a)[3]),                  \
          "r"((b)[0]), "r"((b)[1]))

#define LDSM_X4(r0, r1, r2, r3, addr)                                          \
    asm volatile("ldmatrix.sync.aligned.m8n8.x4.shared.b16 {%0,%1,%2,%3}, [%4];" \
                 : "=r"(r0), "=r"(r1), "=r"(r2), "=r"(r3) : "r"(addr))

__device__ __forceinline__ void cp16(uint32_t sdst, const void* g) {
    asm volatile("cp.async.cg.shared.global [%0], [%1], 16;" :: "r"(sdst), "l"(g));
}
#define CP_COMMIT() asm volatile("cp.async.commit_group;" ::: "memory")
#define CP_WAIT(n) asm volatile("cp.async.wait_group %0;" :: "n"(n) : "memory")

__device__ __forceinline__ void issue_stage(uint32_t tb, int k0,
                                            const __half* gX, const __half* gW,
                                            int tid) {
    // X: 128 rows x 8 chunks = 1024; W same. 128 threads -> 8 each per tile.
    #pragma unroll
    for (int j = 0; j < 8; j++) {
        int q = tid + 128 * j;
        int r = q >> 3, c = q & 7;
        cp16(tb + OFF_X + r * ROWB + c * 16, gX + (size_t)r * K + k0 + c * 8);
    }
    #pragma unroll
    for (int j = 0; j < 8; j++) {
        int q = tid + 128 * j;
        int r = q >> 3, c = q & 7;
        cp16(tb + OFF_W + r * ROWB + c * 16, gW + (size_t)r * K + k0 + c * 8);
    }
    CP_COMMIT();
}

// Load one kk-step's fragments (A: 4 m-tiles, B: 8 n-subtiles)
__device__ __forceinline__ void load_frags(uint32_t tb, int kk, int wm, int wn,
                                           int lrow, int lcol,
                                           uint32_t a[4][4], uint32_t b[8][2]) {
    const uint32_t kbyte = kk * 32 + lcol * 16;
    #pragma unroll
    for (int np = 0; np < 4; np++) {
        uint32_t base = tb + OFF_W + (wn * 64 + np * 16 + lrow) * ROWB + kbyte;
        uint32_t t0, t1, t2, t3;
        LDSM_X4(t0, t1, t2, t3, base);
        b[2 * np][0] = t0; b[2 * np + 1][0] = t1;
        b[2 * np][1] = t2; b[2 * np + 1][1] = t3;
    }
    #pragma unroll
    for (int mt = 0; mt < 4; mt++) {
        uint32_t base = tb + OFF_X + (wm * 64 + mt * 16 + lrow) * ROWB + kbyte;
        LDSM_X4(a[mt][0], a[mt][1], a[mt][2], a[mt][3], base);
    }
}

__device__ __forceinline__ void mma_all(float acc[4][8][4],
                                        uint32_t a[4][4], uint32_t b[8][2]) {
    #pragma unroll
    for (int mt = 0; mt < 4; mt++)
        #pragma unroll
        for (int nt = 0; nt < 8; nt++)
            MMA_FP16(acc[mt][nt], a[mt], b[nt]);
}

__global__ __launch_bounds__(128, 2)
void gemm_fp16_kernel(const float* __restrict__ bias, float* __restrict__ C) {
    extern __shared__ __align__(1024) char smem[];
    uint32_t sb;
    asm("{ .reg .u64 t; cvta.to.shared.u64 t, %1; cvt.u32.u64 %0, t; }"
        : "=r"(sb) : "l"(smem));

    const int tid = threadIdx.x;
    const int warp = tid >> 5;
    const int lane = tid & 31;
    const int wm = warp >> 1;  // 0..1 (64 rows each)
    const int wn = warp & 1;   // 0..1 (64 cols each)
    const int lrow = lane & 15;
    const int lcol = lane >> 4;

    // Supertile raster: groups of 16 N-tiles, M-major within each group
    int lin = blockIdx.x;
    int gid = lin >> 10;            // / (16*64)
    int rem = lin & 1023;
    int n0 = gid * 16;
    int width = min(16, TN_TILES - n0);
    int mT = rem / width;
    int nT = n0 + rem % width;
    const int mBase = mT * BM;
    const int nBase = nT * BN;

    const __half* gX = g_Xh + (size_t)mBase * K;
    const __half* gW = g_Wh + (size_t)nBase * K;

    float acc[4][8][4];
    #pragma unroll
    for (int a = 0; a < 4; a++)
        #pragma unroll
        for (int b = 0; b < 8; b++)
            #pragma unroll
            for (int c = 0; c < 4; c++) acc[a][b][c] = 0.0f;

    issue_stage(sb + 0 * STAGE_BYTES, 0 * BK, gX, gW, tid);
    issue_stage(sb + 1 * STAGE_BYTES, 1 * BK, gX, gW, tid);

    int slot = 0;
    for (int s = 0; s < NSTAGES_K; s++) {
        if (s + 1 < NSTAGES_K) { CP_WAIT(1); } else { CP_WAIT(0); }
        __syncthreads();   // also guards reuse of slot (s+2)%3 (read at s-1)
        if (s + 2 < NSTAGES_K) {
            int wslot = slot + 2; if (wslot >= NSLOTS) wslot -= NSLOTS;
            issue_stage(sb + wslot * STAGE_BYTES, (s + 2) * BK, gX, gW, tid);
        }

        // compute with register double-buffered fragments over 4 kk-steps
        const uint32_t tb = sb + slot * STAGE_BYTES;
        uint32_t af[2][4][4], bf[2][8][2];
        load_frags(tb, 0, wm, wn, lrow, lcol, af[0], bf[0]);
        #pragma unroll
        for (int kk = 0; kk < 4; kk++) {
            if (kk < 3)
                load_frags(tb, kk + 1, wm, wn, lrow, lcol,
                           af[(kk + 1) & 1], bf[(kk + 1) & 1]);
            mma_all(acc, af[kk & 1], bf[kk & 1]);
        }

        slot++;
        if (slot == NSLOTS) slot = 0;
    }

    // Epilogue: add bias, write fp32
    const int qrow = lane >> 2;
    const int qc = (lane & 3) * 2;
    #pragma unroll
    for (int nt = 0; nt < 8; nt++) {
        int col = nBase + wn * 64 + nt * 8 + qc;
        float2 bs = *(const float2*)(bias + col);
        #pragma unroll
        for (int mt = 0; mt < 4; mt++) {
            int row = mBase + wm * 64 + mt * 16 + qrow;
            float2 v0 = make_float2(acc[mt][nt][0] + bs.x, acc[mt][nt][1] + bs.y);
            float2 v1 = make_float2(acc[mt][nt][2] + bs.x, acc[mt][nt][3] + bs.y);
            *(float2*)(C + (size_t)row * N + col) = v0;
            *(float2*)(C + (size_t)(row + 8) * N + col) = v1;
        }
    }
}

// ---------------------------------------------------------------------------
// Launch
// ---------------------------------------------------------------------------
extern "C" void kernel_launch(void* const* d_in, const int* in_sizes, int n_in,
                              void* d_out, int out_size) {
    const float* x    = (const float*)d_in[0];
    const float* W    = (const float*)d_in[1];
    const float* bias = (const float*)d_in[2];
    const float* B    = (const float*)d_in[3];
    const float* A    = (const float*)d_in[4];
    float* out = (float*)d_out;

    size_t n4 = (size_t)M * K / 4;
    conv_x_kernel<<<(unsigned)((n4 + 255) / 256), 256>>>((const float4*)x, n4);
    fold_w_kernel<<<dim3(K / FI, N / FO), 256>>>(W, B, A);

    cudaFuncSetAttribute(gemm_fp16_kernel,
                         cudaFuncAttributeMaxDynamicSharedMemorySize, SMEM_TOTAL);
    gemm_fp16_kernel<<<TM_TILES * TN_TILES, 128, SMEM_TOTAL>>>(bias, out);
}